// round 3
// baseline (speedup 1.0000x reference)
#include <cuda_runtime.h>
#include <cuda_bf16.h>

#define N_NODES    100000
#define OUTPUT_DIM 128
#define KEEP_INV   (1.0f / 0.9f)

// Static device scratch (no allocations allowed)
__device__ int g_mask_mode;              // 0 = uint8/bool, 1 = int32, 2 = float32
__device__ int g_row_start[N_NODES + 1]; // CSR row pointers

// ---------------------------------------------------------------------------
// Kernel 0: classify keep_mask storage dtype from byte statistics.
// keep_prob = 0.9:
//   uint8 layout  -> ~90% of first 1024 bytes equal 0x01
//   int32 layout  -> ints equal to 1 ~90% of the time, but bytes==1 only ~22%
//   float32 layout-> floats equal 1.0f ~90% of the time, bytes==1 ~0%
// Deterministic: same input -> same classification every launch.
// ---------------------------------------------------------------------------
__global__ void detect_mask_kernel(const unsigned char* __restrict__ m, int nnz) {
    const int n = nnz < 1024 ? nnz : 1024;
    int ones_u8 = 0, ones_i32 = 0, ones_f32 = 0;
    const int*   mi = (const int*)m;
    const float* mf = (const float*)m;
    for (int i = 0; i < n; ++i) {
        if (m[i] == 1)      ones_u8++;
        if (mi[i] == 1)     ones_i32++;
        if (mf[i] == 1.0f)  ones_f32++;
    }
    int mode;
    if (ones_u8 * 4 > n * 3)        mode = 0;   // >75% bytes are 1 -> byte mask
    else if (ones_i32 * 4 > n * 3)  mode = 1;   // >75% ints are 1  -> int32 mask
    else                            mode = 2;   // fall back to float mask
    g_mask_mode = mode;
}

// ---------------------------------------------------------------------------
// Kernel 1: build CSR row_start from sorted COO rows.
// row_start[r] = first i with rows[i] >= r ; row_start[N_NODES] = nnz.
// ---------------------------------------------------------------------------
__global__ void build_rowptr_kernel(const int* __restrict__ rows, int nnz) {
    int i = blockIdx.x * blockDim.x + threadIdx.x;
    if (i >= nnz) return;
    int r = rows[i];
    int rprev = (i == 0) ? -1 : rows[i - 1];
    for (int x = rprev + 1; x <= r; ++x) g_row_start[x] = i;
    if (i == nnz - 1) {
        for (int x = r + 1; x <= N_NODES; ++x) g_row_start[x] = nnz;
    }
}

// ---------------------------------------------------------------------------
// Kernel 2: one warp per output row. Lane l accumulates columns [4l, 4l+4).
// Lanes cooperatively stage up to 32 nnz (coalesced loads of value/col/mask),
// then shfl-broadcast through the segment. W row read (512B, coalesced float4)
// is the only per-nnz memory op, and it is skipped for dropped nonzeros.
// Exclusive row ownership -> plain float4 store, bias fused, no atomics,
// no output zero-init pass needed.
// ---------------------------------------------------------------------------
__global__ void __launch_bounds__(256)
spmm_warp_per_row_kernel(const float* __restrict__ values,
                         const int*   __restrict__ cols,
                         const void*  __restrict__ mask,
                         const float4* __restrict__ W4,     // [INPUT_DIM][32] float4
                         const float4* __restrict__ bias4,  // [32] float4
                         float4* __restrict__ out4)         // [N_NODES][32] float4
{
    const int warp = (blockIdx.x * blockDim.x + threadIdx.x) >> 5;
    const int lane = threadIdx.x & 31;
    if (warp >= N_NODES) return;

    const int s = g_row_start[warp];
    const int e = g_row_start[warp + 1];
    const int mode = g_mask_mode;

    float4 acc = bias4[lane];

    for (int base = s; base < e; base += 32) {
        const int idx = base + lane;
        float v = 0.0f;
        int   c = 0;
        if (idx < e) {
            float val = values[idx];
            bool keep;
            if (mode == 0)      keep = ((const unsigned char*)mask)[idx] != 0;
            else if (mode == 1) keep = ((const int*)mask)[idx] != 0;
            else                keep = ((const float*)mask)[idx] != 0.0f;
            v = keep ? val * KEEP_INV : 0.0f;
            c = cols[idx];
        }
        const int cnt = (e - base) < 32 ? (e - base) : 32;
        for (int k = 0; k < cnt; ++k) {
            const float vk = __shfl_sync(0xffffffffu, v, k);
            const int   ck = __shfl_sync(0xffffffffu, c, k);
            if (vk != 0.0f) {                       // warp-uniform: skip dropped nnz
                const float4 w = W4[ck * 32 + lane];
                acc.x += vk * w.x;
                acc.y += vk * w.y;
                acc.z += vk * w.z;
                acc.w += vk * w.w;
            }
        }
    }
    out4[warp * 32 + lane] = acc;                   // 512B coalesced per warp
}

// ---------------------------------------------------------------------------
// kernel_launch — inputs per setup_inputs() order:
//   0: values  float32 [NNZ]
//   1: rows    int32   [NNZ] (sorted)
//   2: cols    int32   [NNZ]
//   3: keep_mask (bool-ish, dtype auto-detected)
//   4: weights float32 [INPUT_DIM, 128]
//   5: bias    float32 [128]
// ---------------------------------------------------------------------------
extern "C" void kernel_launch(void* const* d_in, const int* in_sizes, int n_in,
                              void* d_out, int out_size)
{
    const float* values = (const float*)d_in[0];
    const int*   rows   = (const int*)  d_in[1];
    const int*   cols   = (const int*)  d_in[2];
    const void*  mask   =               d_in[3];
    const float4* W4    = (const float4*)d_in[4];
    const float4* bias4 = (const float4*)d_in[5];
    float4* out4        = (float4*)d_out;

    const int nnz = in_sizes[0];

    detect_mask_kernel<<<1, 1>>>((const unsigned char*)mask, nnz);

    {
        int threads = 256;
        int blocks = (nnz + threads - 1) / threads;
        build_rowptr_kernel<<<blocks, threads>>>(rows, nnz);
    }

    {
        const int warps_per_block = 8;                 // 256 threads
        int blocks = (N_NODES + warps_per_block - 1) / warps_per_block;
        spmm_warp_per_row_kernel<<<blocks, 256>>>(values, cols, mask, W4, bias4, out4);
    }
}

// round 4
// speedup vs baseline: 1.3115x; 1.3115x over previous
#include <cuda_runtime.h>
#include <cuda_bf16.h>

#define N_NODES    100000
#define OUTPUT_DIM 128
#define KEEP_INV   (1.0f / 0.9f)

// Static device scratch (no allocations allowed)
__device__ int g_mask_mode;              // 0 = uint8/bool, 1 = int32, 2 = float32
__device__ int g_row_start[N_NODES + 1]; // CSR row pointers

// ---------------------------------------------------------------------------
// Kernel 0: classify keep_mask storage dtype from byte statistics — PARALLEL.
// 256 threads each inspect 4 sample positions; block-reduce the three counts.
// keep_prob = 0.9:
//   uint8 layout  -> ~90% of first 1024 bytes equal 0x01
//   int32 layout  -> ints equal to 1 ~90% of the time, bytes==1 only ~22%
//   float32 layout-> floats equal 1.0f ~90% of the time, bytes==1 ~0%
// Deterministic: same input -> same classification every launch.
// ---------------------------------------------------------------------------
__global__ void __launch_bounds__(256)
detect_mask_kernel(const unsigned char* __restrict__ m, int nnz) {
    const int n = nnz < 1024 ? nnz : 1024;   // sample window (element indices)
    const int tid = threadIdx.x;

    const int*   mi = (const int*)m;
    const float* mf = (const float*)m;

    int u8 = 0, i32 = 0, f32 = 0;
    // 256 threads x 4 strided samples = 1024 positions, coalesced, MLP>=4
    #pragma unroll
    for (int k = 0; k < 4; ++k) {
        int i = tid + k * 256;
        if (i < n) {
            if (m[i]  == 1)    u8++;
            if (mi[i] == 1)    i32++;
            if (mf[i] == 1.0f) f32++;
        }
    }

    __shared__ int s_u8[8], s_i32[8], s_f32[8];
    // warp reduce
    #pragma unroll
    for (int off = 16; off > 0; off >>= 1) {
        u8  += __shfl_down_sync(0xffffffffu, u8,  off);
        i32 += __shfl_down_sync(0xffffffffu, i32, off);
        f32 += __shfl_down_sync(0xffffffffu, f32, off);
    }
    const int wid = tid >> 5, lane = tid & 31;
    if (lane == 0) { s_u8[wid] = u8; s_i32[wid] = i32; s_f32[wid] = f32; }
    __syncthreads();
    if (tid == 0) {
        int tu8 = 0, ti32 = 0, tf32 = 0;
        #pragma unroll
        for (int w = 0; w < 8; ++w) { tu8 += s_u8[w]; ti32 += s_i32[w]; tf32 += s_f32[w]; }
        int mode;
        if (tu8 * 4 > n * 3)        mode = 0;   // >75% bytes are 1 -> byte mask
        else if (ti32 * 4 > n * 3)  mode = 1;   // >75% ints are 1  -> int32 mask
        else                        mode = 2;   // fall back to float mask
        g_mask_mode = mode;
    }
}

// ---------------------------------------------------------------------------
// Kernel 1: build CSR row_start from sorted COO rows.
// row_start[r] = first i with rows[i] >= r ; row_start[N_NODES] = nnz.
// ---------------------------------------------------------------------------
__global__ void build_rowptr_kernel(const int* __restrict__ rows, int nnz) {
    int i = blockIdx.x * blockDim.x + threadIdx.x;
    if (i >= nnz) return;
    int r = rows[i];
    int rprev = (i == 0) ? -1 : rows[i - 1];
    for (int x = rprev + 1; x <= r; ++x) g_row_start[x] = i;
    if (i == nnz - 1) {
        for (int x = r + 1; x <= N_NODES; ++x) g_row_start[x] = nnz;
    }
}

// ---------------------------------------------------------------------------
// Kernel 2: one warp per output row. Lane l accumulates columns [4l, 4l+4).
// Lanes cooperatively stage up to 32 nnz (coalesced loads of value/col/mask),
// then shfl-broadcast through the segment. W row read (512B, coalesced float4)
// is the only per-nnz memory op, and it is skipped for dropped nonzeros.
// Exclusive row ownership -> plain float4 store, bias fused, no atomics.
// ---------------------------------------------------------------------------
__global__ void __launch_bounds__(256)
spmm_warp_per_row_kernel(const float* __restrict__ values,
                         const int*   __restrict__ cols,
                         const void*  __restrict__ mask,
                         const float4* __restrict__ W4,     // [INPUT_DIM][32] float4
                         const float4* __restrict__ bias4,  // [32] float4
                         float4* __restrict__ out4)         // [N_NODES][32] float4
{
    const int warp = (blockIdx.x * blockDim.x + threadIdx.x) >> 5;
    const int lane = threadIdx.x & 31;
    if (warp >= N_NODES) return;

    const int s = g_row_start[warp];
    const int e = g_row_start[warp + 1];
    const int mode = g_mask_mode;

    float4 acc = bias4[lane];

    for (int base = s; base < e; base += 32) {
        const int idx = base + lane;
        float v = 0.0f;
        int   c = 0;
        if (idx < e) {
            float val = values[idx];
            bool keep;
            if (mode == 0)      keep = ((const unsigned char*)mask)[idx] != 0;
            else if (mode == 1) keep = ((const int*)mask)[idx] != 0;
            else                keep = ((const float*)mask)[idx] != 0.0f;
            v = keep ? val * KEEP_INV : 0.0f;
            c = cols[idx];
        }
        const int cnt = (e - base) < 32 ? (e - base) : 32;
        for (int k = 0; k < cnt; ++k) {
            const float vk = __shfl_sync(0xffffffffu, v, k);
            const int   ck = __shfl_sync(0xffffffffu, c, k);
            if (vk != 0.0f) {                       // warp-uniform: skip dropped nnz
                const float4 w = W4[ck * 32 + lane];
                acc.x += vk * w.x;
                acc.y += vk * w.y;
                acc.z += vk * w.z;
                acc.w += vk * w.w;
            }
        }
    }
    out4[warp * 32 + lane] = acc;                   // 512B coalesced per warp
}

// ---------------------------------------------------------------------------
// kernel_launch — inputs per setup_inputs() order:
//   0: values  float32 [NNZ]
//   1: rows    int32   [NNZ] (sorted)
//   2: cols    int32   [NNZ]
//   3: keep_mask (bool-ish, dtype auto-detected)
//   4: weights float32 [INPUT_DIM, 128]
//   5: bias    float32 [128]
// ---------------------------------------------------------------------------
extern "C" void kernel_launch(void* const* d_in, const int* in_sizes, int n_in,
                              void* d_out, int out_size)
{
    const float* values = (const float*)d_in[0];
    const int*   rows   = (const int*)  d_in[1];
    const int*   cols   = (const int*)  d_in[2];
    const void*  mask   =               d_in[3];
    const float4* W4    = (const float4*)d_in[4];
    const float4* bias4 = (const float4*)d_in[5];
    float4* out4        = (float4*)d_out;

    const int nnz = in_sizes[0];

    detect_mask_kernel<<<1, 256>>>((const unsigned char*)mask, nnz);

    {
        int threads = 256;
        int blocks = (nnz + threads - 1) / threads;
        build_rowptr_kernel<<<blocks, threads>>>(rows, nnz);
    }

    {
        const int warps_per_block = 8;                 // 256 threads
        int blocks = (N_NODES + warps_per_block - 1) / warps_per_block;
        spmm_warp_per_row_kernel<<<blocks, 256>>>(values, cols, mask, W4, bias4, out4);
    }
}